// round 1
// baseline (speedup 1.0000x reference)
#include <cuda_runtime.h>
#include <math.h>

#define NB 32
#define NT 256
#define NWARP (NT / 32)

// ---------------- scratch (device globals; no allocation allowed) ------------
__device__ __align__(16) float g_h0[256];
__device__ __align__(16) float g_attlog[32];
__device__ __align__(16) float g_attw[32];
__device__ __align__(16) float g_attnapp[256];
__device__ __align__(16) float g_comb[256];
__device__ __align__(16) float g_gi[768];
__device__ __align__(16) float g_gh[768];
__device__ __align__(16) float g_hnew[256];
__device__ __align__(16) float g_outlog[32];
__device__ unsigned g_barcnt = 0;
__device__ unsigned g_bargen = 0;

// ---------------- helpers ----------------------------------------------------
__device__ __forceinline__ float warp_sum(float v) {
#pragma unroll
    for (int o = 16; o; o >>= 1) v += __shfl_xor_sync(0xffffffffu, v, o);
    return v;
}

__device__ __forceinline__ float warp_max(float v) {
#pragma unroll
    for (int o = 16; o; o >>= 1) v = fmaxf(v, __shfl_xor_sync(0xffffffffu, v, o));
    return v;
}

// Software grid barrier. Safe across CUDA-graph replays: g_barcnt returns to 0
// after every barrier; g_bargen increments monotonically (equality compare, so
// wraparound is harmless). All threads fence their own stores before arrival.
__device__ __forceinline__ void gsync() {
    __threadfence();
    __syncthreads();
    if (threadIdx.x == 0) {
        unsigned gen = *(volatile unsigned*)&g_bargen;
        if (atomicAdd(&g_barcnt, 1u) == NB - 1) {
            g_barcnt = 0;
            __threadfence();
            atomicAdd(&g_bargen, 1u);
        } else {
            while (*(volatile unsigned*)&g_bargen == gen) { }
        }
    }
    __syncthreads();
}

__device__ __forceinline__ float dot4(float4 a, float4 b) {
    return a.x * b.x + a.y * b.y + a.z * b.z + a.w * b.w;
}

// ---------------- fused decoder step -----------------------------------------
__global__ void __launch_bounds__(NT, 1)
attn_decoder_fused(const int* __restrict__ inp,        // [1]
                   const float* __restrict__ hidden,   // [256]
                   const float* __restrict__ enc,      // [20,256]
                   const int* __restrict__ cond,       // [2]
                   const int* __restrict__ is_head,    // [1]
                   const float* __restrict__ emb,      // [29,256]
                   const float* __restrict__ w_l2d,    // [256,264]
                   const float* __restrict__ b_l2d,    // [256]
                   const float* __restrict__ w_attn,   // [20,512]
                   const float* __restrict__ b_attn,   // [20]
                   const float* __restrict__ w_comb,   // [256,512]
                   const float* __restrict__ b_comb,   // [256]
                   const float* __restrict__ w_ih,     // [768,256]
                   const float* __restrict__ w_hh,     // [768,256]
                   const float* __restrict__ b_ih,     // [768]
                   const float* __restrict__ b_hh,     // [768]
                   const float* __restrict__ w_out,    // [29,256]
                   const float* __restrict__ b_out,    // [29]
                   float* __restrict__ out)            // [305] = logits‖h_new‖attn_w
{
    const int tid  = threadIdx.x;
    const int lane = tid & 31;
    const int wrp  = tid >> 5;
    const int gw   = blockIdx.x * NWARP + wrp;   // global warp 0..255

    const float* erow = emb + (*inp) * 256;      // embedded vector [256]

    // ---- S0: hidden transform (latent2decoder) ------------------------------
    if (*is_head) {
        const int c0 = cond[0], c1 = cond[1];
        const int o  = gw;                       // one warp per output row
        const float* wr = w_l2d + o * 264;
        float s = 0.f;
#pragma unroll
        for (int k = 0; k < 8; k++) {
            int i = lane + k * 32;
            s += wr[i] * hidden[i];
        }
        if (lane < 8) {
            float xv = (lane == c0 || lane == 4 + c1) ? 1.f : 0.f;
            s += wr[256 + lane] * xv;
        }
        s = warp_sum(s);
        if (lane == 0) g_h0[o] = s + b_l2d[o];
    } else {
        if (blockIdx.x == 0 && tid < 256) g_h0[tid] = hidden[tid];
    }
    gsync();

    // ---- Phase A: attention logits (warps 0..19) + gh = W_hh h (warps 64..255)
    if (gw < 20) {
        const float* wr = w_attn + gw * 512;
        float s = 0.f;
#pragma unroll
        for (int k = 0; k < 4; k++) {
            int i = lane * 4 + k * 128;
            float4 wv = *(const float4*)(wr + i);
            float4 xv = (k < 2) ? *(const float4*)(erow + i)
                                : *(const float4*)(g_h0 + (i - 256));
            s += dot4(wv, xv);
        }
        s = warp_sum(s);
        if (lane == 0) g_attlog[gw] = s + b_attn[gw];
    }
    if (gw >= 64) {
        const int base = (gw - 64) * 4;          // 192 warps * 4 rows = 768
#pragma unroll
        for (int rr = 0; rr < 4; rr++) {
            const int o = base + rr;
            const float* wr = w_hh + o * 256;
            float s = 0.f;
#pragma unroll
            for (int k = 0; k < 2; k++) {
                int i = lane * 4 + k * 128;
                s += dot4(*(const float4*)(wr + i), *(const float4*)(g_h0 + i));
            }
            s = warp_sum(s);
            if (lane == 0) g_gh[o] = s + b_hh[o];
        }
    }
    gsync();

    // ---- Phase B: softmax over 20 attention logits (block 0, warp 0) --------
    if (blockIdx.x == 0 && wrp == 0) {
        float v = (lane < 20) ? g_attlog[lane] : -1e30f;
        float m = warp_max(v);
        float e = (lane < 20) ? expf(v - m) : 0.f;
        float sum = warp_sum(e);
        float w = e / sum;
        if (lane < 20) { g_attw[lane] = w; out[285 + lane] = w; }
    }
    gsync();

    // ---- Phase C: attn_applied[c] = sum_l w[l] * enc[l][c] ------------------
    {
        const int c = gw;
        float s = (lane < 20) ? g_attw[lane] * enc[lane * 256 + c] : 0.f;
        s = warp_sum(s);
        if (lane == 0) g_attnapp[c] = s;
    }
    gsync();

    // ---- Phase D: comb = relu(W_comb [emb ‖ attn_applied] + b) --------------
    {
        const int o = gw;
        const float* wr = w_comb + o * 512;
        float s = 0.f;
#pragma unroll
        for (int k = 0; k < 4; k++) {
            int i = lane * 4 + k * 128;
            float4 wv = *(const float4*)(wr + i);
            float4 xv = (k < 2) ? *(const float4*)(erow + i)
                                : *(const float4*)(g_attnapp + (i - 256));
            s += dot4(wv, xv);
        }
        s = warp_sum(s);
        if (lane == 0) g_comb[o] = fmaxf(s + b_comb[o], 0.f);
    }
    gsync();

    // ---- Phase E: gi = W_ih comb + b_ih (3 rows per warp) -------------------
    {
#pragma unroll
        for (int rr = 0; rr < 3; rr++) {
            const int o = gw * 3 + rr;
            const float* wr = w_ih + o * 256;
            float s = 0.f;
#pragma unroll
            for (int k = 0; k < 2; k++) {
                int i = lane * 4 + k * 128;
                s += dot4(*(const float4*)(wr + i), *(const float4*)(g_comb + i));
            }
            s = warp_sum(s);
            if (lane == 0) g_gi[o] = s + b_ih[o];
        }
    }
    gsync();

    // ---- Phase F: GRU gates (block 0, 256 threads) --------------------------
    if (blockIdx.x == 0 && tid < 256) {
        const int o = tid;
        float r = 1.f / (1.f + expf(-(g_gi[o]       + g_gh[o])));
        float z = 1.f / (1.f + expf(-(g_gi[256 + o] + g_gh[256 + o])));
        float n = tanhf(g_gi[512 + o] + r * g_gh[512 + o]);
        float h = (1.f - z) * n + z * g_h0[o];
        g_hnew[o] = h;
        out[29 + o] = h;
    }
    gsync();

    // ---- Phase G: output logits (warps 0..28) -------------------------------
    if (gw < 29) {
        const float* wr = w_out + gw * 256;
        float s = 0.f;
#pragma unroll
        for (int k = 0; k < 2; k++) {
            int i = lane * 4 + k * 128;
            s += dot4(*(const float4*)(wr + i), *(const float4*)(g_hnew + i));
        }
        s = warp_sum(s);
        if (lane == 0) g_outlog[gw] = s + b_out[gw];
    }
    gsync();

    // ---- Phase H: log_softmax over 29 (block 0, warp 0) ---------------------
    if (blockIdx.x == 0 && wrp == 0) {
        float v = (lane < 29) ? g_outlog[lane] : -1e30f;
        float m = warp_max(v);
        float e = (lane < 29) ? expf(v - m) : 0.f;
        float sum = warp_sum(e);
        float ls = logf(sum);
        if (lane < 29) out[lane] = v - m - ls;
    }
}

// ---------------- launch ------------------------------------------------------
extern "C" void kernel_launch(void* const* d_in, const int* in_sizes, int n_in,
                              void* d_out, int out_size) {
    (void)in_sizes; (void)n_in; (void)out_size;
    const int*   inp     = (const int*)  d_in[0];
    const float* hidden  = (const float*)d_in[1];
    const float* enc     = (const float*)d_in[2];
    const int*   cond    = (const int*)  d_in[3];
    const int*   is_head = (const int*)  d_in[4];
    const float* emb     = (const float*)d_in[5];
    const float* w_l2d   = (const float*)d_in[6];
    const float* b_l2d   = (const float*)d_in[7];
    const float* w_attn  = (const float*)d_in[8];
    const float* b_attn  = (const float*)d_in[9];
    const float* w_comb  = (const float*)d_in[10];
    const float* b_comb  = (const float*)d_in[11];
    const float* w_ih    = (const float*)d_in[12];
    const float* w_hh    = (const float*)d_in[13];
    const float* b_ih    = (const float*)d_in[14];
    const float* b_hh    = (const float*)d_in[15];
    const float* w_out   = (const float*)d_in[16];
    const float* b_out   = (const float*)d_in[17];

    attn_decoder_fused<<<NB, NT>>>(inp, hidden, enc, cond, is_head, emb,
                                   w_l2d, b_l2d, w_attn, b_attn,
                                   w_comb, b_comb, w_ih, w_hh, b_ih, b_hh,
                                   w_out, b_out, (float*)d_out);
}

// round 2
// speedup vs baseline: 1.3750x; 1.3750x over previous
#include <cuda_runtime.h>
#include <math.h>

#define NB 32
#define NT 256
#define NWARP (NT / 32)

// ---------------- scratch (device globals; no allocation allowed) ------------
__device__ __align__(16) float g_h0[256];
__device__ __align__(16) float g_attlog[32];
__device__ __align__(16) float g_gh[768];
__device__ __align__(16) float g_comb[256];
__device__ __align__(16) float g_hnew[256];
__device__ unsigned g_barcnt = 0;
__device__ unsigned g_bargen = 0;

// ---------------- helpers ----------------------------------------------------
__device__ __forceinline__ float warp_sum(float v) {
#pragma unroll
    for (int o = 16; o; o >>= 1) v += __shfl_xor_sync(0xffffffffu, v, o);
    return v;
}
__device__ __forceinline__ float warp_max(float v) {
#pragma unroll
    for (int o = 16; o; o >>= 1) v = fmaxf(v, __shfl_xor_sync(0xffffffffu, v, o));
    return v;
}

// Grid barrier; graph-replay safe (count returns to 0, gen compared by equality).
__device__ __forceinline__ void gsync() {
    __threadfence();
    __syncthreads();
    if (threadIdx.x == 0) {
        unsigned gen = *(volatile unsigned*)&g_bargen;
        if (atomicAdd(&g_barcnt, 1u) == NB - 1) {
            g_barcnt = 0;
            __threadfence();
            atomicAdd(&g_bargen, 1u);
        } else {
            while (*(volatile unsigned*)&g_bargen == gen) { }
        }
    }
    __syncthreads();
}

__device__ __forceinline__ float dot4(float4 a, float4 b) {
    return a.x * b.x + a.y * b.y + a.z * b.z + a.w * b.w;
}

// 256-length dot: weight row from gmem, x from shared. Result in ALL lanes.
__device__ __forceinline__ float dot256(const float* __restrict__ w,
                                        const float* s, int lane) {
    float4 w0 = *(const float4*)(w + lane * 4);
    float4 w1 = *(const float4*)(w + 128 + lane * 4);
    float4 x0 = *(const float4*)(s + lane * 4);
    float4 x1 = *(const float4*)(s + 128 + lane * 4);
    return warp_sum(dot4(w0, x0) + dot4(w1, x1));
}

// ---------------- fused decoder step -----------------------------------------
__global__ void __launch_bounds__(NT, 1)
attn_decoder_fused(const int* __restrict__ inp,
                   const float* __restrict__ hidden,   // [256]
                   const float* __restrict__ enc,      // [20,256]
                   const int* __restrict__ cond,       // [2]
                   const int* __restrict__ is_head,    // [1]
                   const float* __restrict__ emb,      // [29,256]
                   const float* __restrict__ w_l2d,    // [256,264]
                   const float* __restrict__ b_l2d,
                   const float* __restrict__ w_attn,   // [20,512]
                   const float* __restrict__ b_attn,
                   const float* __restrict__ w_comb,   // [256,512]
                   const float* __restrict__ b_comb,
                   const float* __restrict__ w_ih,     // [768,256]
                   const float* __restrict__ w_hh,     // [768,256]
                   const float* __restrict__ b_ih,
                   const float* __restrict__ b_hh,
                   const float* __restrict__ w_out,    // [29,256]
                   const float* __restrict__ b_out,
                   float* __restrict__ out)            // [305]
{
    __shared__ __align__(16) float sA[256];
    __shared__ __align__(16) float sB[256];
    __shared__ float sW[32];

    const int tid  = threadIdx.x;
    const int lane = tid & 31;
    const int wrp  = tid >> 5;
    const int gw   = blockIdx.x * NWARP + wrp;   // 0..255

    const int head = *is_head;
    const float* erow = emb + (*inp) * 256;

    // stage hidden + embedded row into shared
    sA[tid] = hidden[tid];
    sB[tid] = __ldg(erow + tid);
    __syncthreads();

    // ---- P1: h0 row gw (if head), comb_emb partial (register), attn_emb partial
    float h0v = 0.f;                 // h0[gw], all lanes
    if (head) {
        const int c0 = __ldg(cond), c1 = __ldg(cond + 1);
        const float* wr = w_l2d + gw * 264;
        float4 w0 = *(const float4*)(wr + lane * 4);
        float4 w1 = *(const float4*)(wr + 128 + lane * 4);
        float s = dot4(w0, *(const float4*)(sA + lane * 4)) +
                  dot4(w1, *(const float4*)(sA + 128 + lane * 4));
        if (lane < 8) {
            float xv = (lane == c0 || lane == 4 + c1) ? 1.f : 0.f;
            s += wr[256 + lane] * xv;
        }
        h0v = warp_sum(s) + b_l2d[gw];
        if (lane == 0) __stcg(g_h0 + gw, h0v);
    }
    float ce = dot256(w_comb + gw * 512, sB, lane);          // comb emb-half, reg
    float ae = 0.f;
    if (gw < 20) ae = dot256(w_attn + gw * 512, sB, lane);   // attn emb-half, reg
    gsync();                                                 // ---- gb1

    // ---- P2: gh = W_hh h0 (3 rows/warp), attn logits h0-half
    if (head) { sA[tid] = __ldcg(g_h0 + tid); }
    __syncthreads();
    {
        const int o0 = gw * 3;
#pragma unroll
        for (int rr = 0; rr < 3; rr++) {
            const int o = o0 + rr;
            float s = dot256(w_hh + o * 256, sA, lane);
            if (lane == 0) __stcg(g_gh + o, s + b_hh[o]);
        }
    }
    if (gw < 20) {
        float s = dot256(w_attn + gw * 512 + 256, sA, lane);
        if (lane == 0) __stcg(g_attlog + gw, ae + s + b_attn[gw]);
    }
    gsync();                                                 // ---- gb2

    // ---- P3: per-CTA softmax + attn_applied (shared), then comb rows
    if (wrp == 0) {
        float v = (lane < 20) ? __ldcg(g_attlog + lane) : -1e30f;
        float m = warp_max(v);
        float e = (lane < 20) ? expf(v - m) : 0.f;
        float sum = warp_sum(e);
        float w = e / sum;
        if (lane < 20) {
            sW[lane] = w;
            if (blockIdx.x == 0) out[285 + lane] = w;
        }
    }
    __syncthreads();
    {
        float a = 0.f;
#pragma unroll
        for (int l = 0; l < 20; l++) a += sW[l] * __ldg(enc + l * 256 + tid);
        sB[tid] = a;                                         // attn_applied
    }
    __syncthreads();
    {
        float s = dot256(w_comb + gw * 512 + 256, sB, lane);
        if (lane == 0) __stcg(g_comb + gw, fmaxf(s + ce + b_comb[gw], 0.f));
    }
    gsync();                                                 // ---- gb3

    // ---- P4: gi rows + fused GRU for element gw
    sA[tid] = __ldcg(g_comb + tid);
    __syncthreads();
    {
        float gr = dot256(w_ih + gw * 256,             sA, lane) + b_ih[gw];
        float gz = dot256(w_ih + (256 + gw) * 256,     sA, lane) + b_ih[256 + gw];
        float gn = dot256(w_ih + (512 + gw) * 256,     sA, lane) + b_ih[512 + gw];
        if (lane == 0) {
            float hr = __ldcg(g_gh + gw);
            float hz = __ldcg(g_gh + 256 + gw);
            float hn = __ldcg(g_gh + 512 + gw);
            float h0o = head ? h0v : __ldg(hidden + gw);
            float r = 1.f / (1.f + expf(-(gr + hr)));
            float z = 1.f / (1.f + expf(-(gz + hz)));
            float n = tanhf(gn + r * hn);
            float h = (1.f - z) * n + z * h0o;
            __stcg(g_hnew + gw, h);
            out[29 + gw] = h;
        }
    }
    gsync();                                                 // ---- gb4

    if (blockIdx.x != 0) return;

    // ---- P5 (CTA0): output logits + log_softmax
    sA[tid] = __ldcg(g_hnew + tid);
    __syncthreads();
#pragma unroll
    for (int rr = 0; rr < 4; rr++) {
        const int o = wrp * 4 + rr;
        if (o < 29) {
            float s = dot256(w_out + o * 256, sA, lane);
            if (lane == 0) sW[o] = s + b_out[o];
        }
    }
    __syncthreads();
    if (wrp == 0) {
        float v = (lane < 29) ? sW[lane] : -1e30f;
        float m = warp_max(v);
        float e = (lane < 29) ? expf(v - m) : 0.f;
        float sum = warp_sum(e);
        float ls = logf(sum);
        if (lane < 29) out[lane] = v - m - ls;
    }
}

// ---------------- launch ------------------------------------------------------
extern "C" void kernel_launch(void* const* d_in, const int* in_sizes, int n_in,
                              void* d_out, int out_size) {
    (void)in_sizes; (void)n_in; (void)out_size;
    attn_decoder_fused<<<NB, NT>>>(
        (const int*)d_in[0],  (const float*)d_in[1], (const float*)d_in[2],
        (const int*)d_in[3],  (const int*)d_in[4],   (const float*)d_in[5],
        (const float*)d_in[6],(const float*)d_in[7], (const float*)d_in[8],
        (const float*)d_in[9],(const float*)d_in[10],(const float*)d_in[11],
        (const float*)d_in[12],(const float*)d_in[13],(const float*)d_in[14],
        (const float*)d_in[15],(const float*)d_in[16],(const float*)d_in[17],
        (float*)d_out);
}